// round 7
// baseline (speedup 1.0000x reference)
#include <cuda_runtime.h>
#include <math.h>

// Problem constants
#define LSEQ 8192
#define NFFT 16384          // 2*LSEQ = 32*32*16
#define DM   768
#define EMB  33
#define FO   64
#define SHIFT_C 0.05f
#define NT   512            // FFT threads per CTA

// Pad 1 float2 per 16: PHYS(i) = i + (i>>4).  (verified conflict-free R5)
#define DPAD 17408
#define SMEM_BYTES (DPAD * (int)sizeof(unsigned long long))   // 139264 B

// ---------------- packed complex: one float2 in a b64 register pair ---------
typedef unsigned long long cplx;

// componentwise-multiplier constants (low 32 bits = real component)
#define K_NEG1 0xBF800000BF800000ULL   // (-1, -1)
#define K_PM   0xBF8000003F800000ULL   // ( 1, -1)
#define K_MP   0x3F800000BF800000ULL   // (-1,  1)

__device__ __forceinline__ cplx cpack(float x, float y) {
    cplx r; asm("mov.b64 %0,{%1,%2};" : "=l"(r) : "f"(x), "f"(y)); return r;
}
__device__ __forceinline__ void cunpack(cplx a, float& x, float& y) {
    asm("mov.b64 {%0,%1},%2;" : "=f"(x), "=f"(y) : "l"(a));
}
__device__ __forceinline__ cplx cswap(cplx a) {
    float x, y; cunpack(a, x, y); return cpack(y, x);
}
__device__ __forceinline__ cplx cadd(cplx a, cplx b) {
    cplx r; asm("add.rn.f32x2 %0,%1,%2;" : "=l"(r) : "l"(a), "l"(b)); return r;
}
__device__ __forceinline__ cplx cfma(cplx a, cplx b, cplx c) {
    cplx r; asm("fma.rn.f32x2 %0,%1,%2,%3;" : "=l"(r) : "l"(a), "l"(b), "l"(c)); return r;
}
__device__ __forceinline__ cplx csub(cplx a, cplx b) { return cfma(b, (cplx)K_NEG1, a); }

// complex multiply by scalar twiddle (wx, wy): 2 FMUL + 2 FFMA
__device__ __forceinline__ cplx cmulf(cplx a, float wx, float wy) {
    float ax, ay; cunpack(a, ax, ay);
    float rx = fmaf(-ay, wy, ax * wx);
    float ry = fmaf( ay, wx, ax * wy);
    return cpack(rx, ry);
}
__device__ __forceinline__ cplx cmulc(cplx a, cplx w) {
    float wx, wy; cunpack(w, wx, wy);
    return cmulf(a, wx, wy);
}

// radix-4 DIF forward core (no twiddle): 8 packed ops
__device__ __forceinline__ void bf4f(cplx x0, cplx x1, cplx x2, cplx x3,
                                     cplx& a0, cplx& a1, cplx& a2, cplx& a3) {
    cplx t0 = cadd(x0, x2), t1 = cfma(x2, (cplx)K_NEG1, x0);
    cplx t2 = cadd(x1, x3), t3 = cfma(x3, (cplx)K_NEG1, x1);
    cplx sw = cswap(t3);
    a0 = cadd(t0, t2);
    a2 = cfma(t2, (cplx)K_NEG1, t0);
    a1 = cfma(sw, (cplx)K_PM, t1);     // t1 - i*t3
    a3 = cfma(sw, (cplx)K_MP, t1);     // t1 + i*t3
}
// radix-4 inverse core (unscaled)
__device__ __forceinline__ void bf4i(cplx x0, cplx x1, cplx x2, cplx x3,
                                     cplx& a0, cplx& a1, cplx& a2, cplx& a3) {
    cplx t0 = cadd(x0, x2), t1 = cfma(x2, (cplx)K_NEG1, x0);
    cplx t2 = cadd(x1, x3), t3 = cfma(x3, (cplx)K_NEG1, x1);
    cplx sw = cswap(t3);
    a0 = cadd(t0, t2);
    a2 = cfma(t2, (cplx)K_NEG1, t0);
    a1 = cfma(sw, (cplx)K_MP, t1);     // t1 + i*t3
    a3 = cfma(sw, (cplx)K_PM, t1);     // t1 - i*t3
}

// ---------------- scratch (device globals: no allocations allowed) ----------
__device__ float g_S[LSEQ * FO];                         // post-MLP activations
__device__ float g_k[DM * LSEQ];                         // filter k[d][l]
__device__ __align__(16) cplx g_Kf[(size_t)DM * NFFT];   // (spectrum + D)/N, scrambled

// e^{-2*pi*i*c/32}, c = 0..7 (constexpr -> immediates)
__device__ static constexpr float R32X[8] = {
    1.0f, 0.98078528040323044f, 0.92387953251128674f, 0.83146961230254524f,
    0.70710678118654752f, 0.55557023301960222f, 0.38268343236508977f, 0.19509032201612827f };
__device__ static constexpr float R32Y[8] = {
    0.0f, -0.19509032201612827f, -0.38268343236508977f, -0.55557023301960222f,
    -0.70710678118654752f, -0.83146961230254524f, -0.92387953251128674f, -0.98078528040323044f };
// e^{-2*pi*i*c/16}, c = 0..3
__device__ static constexpr float R16X[4] = {
    1.0f, 0.92387953251128674f, 0.70710678118654752f, 0.38268343236508977f };
__device__ static constexpr float R16Y[4] = {
    0.0f, -0.38268343236508977f, -0.70710678118654752f, -0.92387953251128674f };
#define R8X 0.70710678118654752f

// ---------------- register radix-32 (4*4*2 DIF), external span S = 1<<LS ----
// HALF: x[16..31] implicitly zero on entry.
template<int LS, bool HALF>
__device__ __forceinline__ void fft32_fwd(cplx* x, int j) {
    const float C = -6.2831853071795864769f / (float)(1 << (LS + 5));
    float sb, cb;
    __sincosf(C * (float)j, &sb, &cb);
    // stage A: span 8
    #pragma unroll
    for (int c = 0; c < 8; c++) {
        float w1x = fmaf(-sb, R32Y[c], cb * R32X[c]);
        float w1y = fmaf( sb, R32X[c], cb * R32Y[c]);
        float w2x = fmaf(-w1y, w1y, w1x * w1x), w2y = 2.0f * w1x * w1y;
        float w3x = fmaf(-w2y, w1y, w2x * w1x), w3y = fmaf(w2y, w1x, w2x * w1y);
        cplx a0, a1, a2, a3;
        if (HALF) {
            cplx x0 = x[c], x1 = x[c + 8];
            cplx sw = cswap(x1);
            a0 = cadd(x0, x1);
            a2 = cfma(x1, (cplx)K_NEG1, x0);
            a1 = cfma(sw, (cplx)K_PM, x0);           // x0 - i*x1
            a3 = cfma(sw, (cplx)K_MP, x0);           // x0 + i*x1
        } else {
            bf4f(x[c], x[c+8], x[c+16], x[c+24], a0, a1, a2, a3);
        }
        x[c]      = a0;
        x[c + 8]  = cmulf(a1, w1x, w1y);
        x[c + 16] = cmulf(a2, w2x, w2y);
        x[c + 24] = cmulf(a3, w3x, w3y);
    }
    // b powers (scalar)
    float b2x = fmaf(-sb, sb, cb * cb),  b2y = 2.0f * cb * sb;
    float b4x = fmaf(-b2y, b2y, b2x * b2x), b4y = 2.0f * b2x * b2y;
    // stage B: span 2, twiddles b4 and b4*e^{-i pi/4} (+ squares/cubes), precomputed
    float wx[2], wy[2], w2xA[2], w2yA[2], w3xA[2], w3yA[2];
    wx[0] = b4x; wy[0] = b4y;
    wx[1] = (b4x + b4y) * R8X;                        // b4 * (R8X, -R8X)
    wy[1] = (b4y - b4x) * R8X;
    #pragma unroll
    for (int c2 = 0; c2 < 2; c2++) {
        w2xA[c2] = fmaf(-wy[c2], wy[c2], wx[c2] * wx[c2]);
        w2yA[c2] = 2.0f * wx[c2] * wy[c2];
        w3xA[c2] = fmaf(-w2yA[c2], wy[c2], w2xA[c2] * wx[c2]);
        w3yA[c2] = fmaf( w2yA[c2], wx[c2], w2xA[c2] * wy[c2]);
    }
    #pragma unroll
    for (int g = 0; g < 4; g++) {
        #pragma unroll
        for (int c2 = 0; c2 < 2; c2++) {
            const int i = 8 * g + c2;
            cplx a0, a1, a2, a3;
            bf4f(x[i], x[i+2], x[i+4], x[i+6], a0, a1, a2, a3);
            x[i]     = a0;
            x[i + 2] = cmulf(a1, wx[c2],   wy[c2]);
            x[i + 4] = cmulf(a2, w2xA[c2], w2yA[c2]);
            x[i + 6] = cmulf(a3, w3xA[c2], w3yA[c2]);
        }
    }
    float b8x  = fmaf(-b4y, b4y, b4x * b4x), b8y = 2.0f * b4x * b4y;
    float b16x = fmaf(-b8y, b8y, b8x * b8x), b16y = 2.0f * b8x * b8y;
    // stage C: radix-2, span 1
    #pragma unroll
    for (int m = 0; m < 16; m++) {
        cplx x0 = x[2*m], x1 = x[2*m + 1];
        x[2*m]     = cadd(x0, x1);
        x[2*m + 1] = cmulf(cfma(x1, (cplx)K_NEG1, x0), b16x, b16y);
    }
}

// Inverse (unscaled, gain 32).  HALFOUT: only outputs r<16 are produced.
template<int LS, bool HALFOUT>
__device__ __forceinline__ void fft32_inv(cplx* x, int j) {
    const float C = -6.2831853071795864769f / (float)(1 << (LS + 5));
    float sb, cb;
    __sincosf(C * (float)j, &sb, &cb);
    const float bx = cb, by = -sb;                    // conj
    float b2x = fmaf(-by, by, bx * bx),  b2y = 2.0f * bx * by;
    float b4x = fmaf(-b2y, b2y, b2x * b2x), b4y = 2.0f * b2x * b2y;
    float b8x = fmaf(-b4y, b4y, b4x * b4x), b8y = 2.0f * b4x * b4y;
    float b16x = fmaf(-b8y, b8y, b8x * b8x), b16y = 2.0f * b8x * b8y;
    // stage C'
    #pragma unroll
    for (int m = 0; m < 16; m++) {
        cplx z1 = cmulf(x[2*m + 1], b16x, b16y);
        cplx x0 = x[2*m];
        x[2*m]     = cadd(x0, z1);
        x[2*m + 1] = cfma(z1, (cplx)K_NEG1, x0);
    }
    // stage B': twiddles b4, b4*e^{+i pi/4}
    float wx[2], wy[2], w2xA[2], w2yA[2], w3xA[2], w3yA[2];
    wx[0] = b4x; wy[0] = b4y;
    wx[1] = (b4x - b4y) * R8X;                        // b4 * (R8X, +R8X)
    wy[1] = (b4y + b4x) * R8X;
    #pragma unroll
    for (int c2 = 0; c2 < 2; c2++) {
        w2xA[c2] = fmaf(-wy[c2], wy[c2], wx[c2] * wx[c2]);
        w2yA[c2] = 2.0f * wx[c2] * wy[c2];
        w3xA[c2] = fmaf(-w2yA[c2], wy[c2], w2xA[c2] * wx[c2]);
        w3yA[c2] = fmaf( w2yA[c2], wx[c2], w2xA[c2] * wy[c2]);
    }
    #pragma unroll
    for (int g = 0; g < 4; g++) {
        #pragma unroll
        for (int c2 = 0; c2 < 2; c2++) {
            const int i = 8 * g + c2;
            cplx z0 = x[i];
            cplx z1 = cmulf(x[i + 2], wx[c2],   wy[c2]);
            cplx z2 = cmulf(x[i + 4], w2xA[c2], w2yA[c2]);
            cplx z3 = cmulf(x[i + 6], w3xA[c2], w3yA[c2]);
            bf4i(z0, z1, z2, z3, x[i], x[i+2], x[i+4], x[i+6]);
        }
    }
    // stage A': w1 = bconj * conj(rot_c)
    #pragma unroll
    for (int c = 0; c < 8; c++) {
        float w1x = fmaf( by, R32Y[c], bx * R32X[c]);  // (bx+iby)(cx-icy): re = bx*cx + by*cy
        float w1y = fmaf(-bx, R32Y[c], by * R32X[c]);  //                  im = by*cx - bx*cy
        float w2x = fmaf(-w1y, w1y, w1x * w1x), w2y = 2.0f * w1x * w1y;
        float w3x = fmaf(-w2y, w1y, w2x * w1x), w3y = fmaf(w2y, w1x, w2x * w1y);
        cplx z0 = x[c];
        cplx z1 = cmulf(x[c + 8],  w1x, w1y);
        cplx z2 = cmulf(x[c + 16], w2x, w2y);
        cplx z3 = cmulf(x[c + 24], w3x, w3y);
        if (HALFOUT) {
            cplx t0 = cadd(z0, z2), t1 = cfma(z2, (cplx)K_NEG1, z0);
            cplx t2 = cadd(z1, z3), t3 = cfma(z3, (cplx)K_NEG1, z1);
            cplx sw = cswap(t3);
            x[c]     = cadd(t0, t2);
            x[c + 8] = cfma(sw, (cplx)K_MP, t1);       // t1 + i*t3
        } else {
            bf4i(z0, z1, z2, z3, x[c], x[c+8], x[c+16], x[c+24]);
        }
    }
}

// ---------------- 16-point cores, all-constant twiddles ---------------------
__device__ __forceinline__ void fft16c_fwd(cplx* x) {
    #pragma unroll
    for (int c = 0; c < 4; c++) {
        float w1x = R16X[c], w1y = R16Y[c];
        float w2x = fmaf(-w1y, w1y, w1x * w1x), w2y = 2.0f * w1x * w1y;
        float w3x = fmaf(-w2y, w1y, w2x * w1x), w3y = fmaf(w2y, w1x, w2x * w1y);
        cplx a0, a1, a2, a3;
        bf4f(x[c], x[c+4], x[c+8], x[c+12], a0, a1, a2, a3);
        x[c]      = a0;
        x[c + 4]  = cmulf(a1, w1x, w1y);
        x[c + 8]  = cmulf(a2, w2x, w2y);
        x[c + 12] = cmulf(a3, w3x, w3y);
    }
    #pragma unroll
    for (int m = 0; m < 4; m++) {
        cplx a0, a1, a2, a3;
        bf4f(x[4*m], x[4*m+1], x[4*m+2], x[4*m+3], a0, a1, a2, a3);
        x[4*m] = a0; x[4*m+1] = a1; x[4*m+2] = a2; x[4*m+3] = a3;
    }
}
__device__ __forceinline__ void fft16c_inv(cplx* x) {
    #pragma unroll
    for (int m = 0; m < 4; m++) {
        cplx a0, a1, a2, a3;
        bf4i(x[4*m], x[4*m+1], x[4*m+2], x[4*m+3], a0, a1, a2, a3);
        x[4*m] = a0; x[4*m+1] = a1; x[4*m+2] = a2; x[4*m+3] = a3;
    }
    #pragma unroll
    for (int c = 0; c < 4; c++) {
        float w1x = R16X[c], w1y = -R16Y[c];          // conj
        float w2x = fmaf(-w1y, w1y, w1x * w1x), w2y = 2.0f * w1x * w1y;
        float w3x = fmaf(-w2y, w1y, w2x * w1x), w3y = fmaf(w2y, w1x, w2x * w1y);
        cplx z1 = cmulf(x[c + 4],  w1x, w1y);
        cplx z2 = cmulf(x[c + 8],  w2x, w2y);
        cplx z3 = cmulf(x[c + 12], w3x, w3y);
        bf4i(x[c], z1, z2, z3, x[c], x[c+4], x[c+8], x[c+12]);
    }
}

// ---------------- filter MLP stages 1-3 -------------------------------------
__global__ void mlp_kernel(const float* __restrict__ z, const float* __restrict__ freq,
                           const float* __restrict__ W1, const float* __restrict__ b1,
                           const float* __restrict__ W2, const float* __restrict__ b2,
                           const float* __restrict__ W3, const float* __restrict__ b3) {
    __shared__ float zs[4][EMB];
    __shared__ float as[4][FO];
    __shared__ float bs[4][FO];
    const int tid = threadIdx.x;
    const int lg  = tid >> 6;
    const int f   = tid & 63;
    const int l   = blockIdx.x * 4 + lg;

    if (f < EMB) zs[lg][f] = z[l * EMB + f];
    __syncthreads();

    const float fr = freq[f];

    float acc = b1[f];
    #pragma unroll
    for (int e = 0; e < EMB; e++) acc += zs[lg][e] * W1[e * FO + f];
    as[lg][f] = sinf(fr * acc);
    __syncthreads();

    acc = b2[f];
    #pragma unroll
    for (int e = 0; e < FO; e++) acc += as[lg][e] * W2[e * FO + f];
    bs[lg][f] = sinf(fr * acc);
    __syncthreads();

    acc = b3[f];
    #pragma unroll
    for (int e = 0; e < FO; e++) acc += bs[lg][e] * W3[e * FO + f];
    g_S[l * FO + f] = sinf(fr * acc);
}

// ---------------- output projection + exponential modulation ----------------
__global__ void filt_kernel(const float* __restrict__ Wout, const float* __restrict__ t,
                            const float* __restrict__ deltas) {
    __shared__ float Ss[32][FO];
    __shared__ float Ws[FO][128];
    const int tid = threadIdx.x;
    const int l0  = blockIdx.x * 32;
    const int d0  = blockIdx.y * 128;

    for (int i = tid; i < 32 * FO; i += 256)
        Ss[i >> 6][i & 63] = g_S[(l0 + (i >> 6)) * FO + (i & 63)];
    for (int i = tid; i < FO * 128; i += 256)
        Ws[i >> 7][i & 127] = Wout[(i >> 7) * DM + d0 + (i & 127)];
    __syncthreads();

    const int dl  = tid & 127;
    const int lgp = tid >> 7;
    float acc[16];
    #pragma unroll
    for (int i = 0; i < 16; i++) acc[i] = 0.0f;
    #pragma unroll
    for (int f = 0; f < FO; f++) {
        const float w = Ws[f][dl];
        #pragma unroll
        for (int i = 0; i < 16; i++) acc[i] += Ss[lgp * 16 + i][f] * w;
    }
    const int d = d0 + dl;
    const float ad = fabsf(deltas[d]);
    #pragma unroll
    for (int i = 0; i < 16; i++) {
        const int l = l0 + lgp * 16 + i;
        g_k[(size_t)d * LSEQ + l] = acc[i] * (expf(-t[l] * ad) + SHIFT_C);
    }
}

// ---------------- kernel spectrum (+D baked in) -----------------------------
__global__ void __launch_bounds__(NT, 1)
kf_kernel(const float* __restrict__ Dbias) {
    extern __shared__ cplx d[];
    const int tid = threadIdx.x;
    const int ch  = blockIdx.x;

    const float* krow = g_k + (size_t)ch * LSEQ;
    const int jb = tid + (tid >> 4);                     // PHYS(tid)

    // P1: radix-32, S=512; top half zero
    {
        cplx xv[32];
        #pragma unroll
        for (int r = 0; r < 16; r++)
            xv[r] = cpack(krow[tid + (r << 9)], 0.0f);
        fft32_fwd<9, true>(xv, tid);
        #pragma unroll
        for (int r = 0; r < 32; r++) d[jb + 544 * r] = xv[r];
    }
    __syncthreads();

    const int j2 = tid & 15;
    const int b0 = (tid >> 4) * 544 + j2;

    // P2: radix-32, S=16
    {
        cplx xv[32];
        #pragma unroll
        for (int r = 0; r < 32; r++) xv[r] = d[b0 + 17 * r];
        fft32_fwd<4, false>(xv, j2);
        #pragma unroll
        for (int r = 0; r < 32; r++) d[b0 + 17 * r] = xv[r];
    }
    __syncthreads();

    // P3: const-twiddle fwd16 + bake (spec + D)/N, store to g_Kf
    cplx* outp = g_Kf + (size_t)ch * NFFT;
    const float sc = 1.0f / (float)NFFT;
    const float Dd = Dbias[ch];
    const cplx sC  = cpack(sc, sc);
    const cplx off = cpack(Dd * sc, 0.0f);
    #pragma unroll
    for (int k = 0; k < 2; k++) {
        const int q  = tid + k * NT;
        const int pb = 17 * q;                           // PHYS(16q)
        cplx xv[16];
        #pragma unroll
        for (int r = 0; r < 16; r++) xv[r] = d[pb + r];
        fft16c_fwd(xv);
        ulonglong2* o2 = reinterpret_cast<ulonglong2*>(outp + 16 * q);
        #pragma unroll
        for (int i = 0; i < 8; i++) {
            ulonglong2 v;
            v.x = cfma(xv[2*i],     sC, off);
            v.y = cfma(xv[2*i + 1], sC, off);
            o2[i] = v;
        }
    }
}

// ---------------- conv ------------------------------------------------------
__global__ void __launch_bounds__(NT, 1)
conv_kernel(const float* __restrict__ x, float* __restrict__ out) {
    extern __shared__ cplx d[];
    const int tid = threadIdx.x;
    const int ch  = blockIdx.x;
    const int p   = blockIdx.y;                          // batch pair

    const float* u0 = x + ((size_t)(2*p)     * DM + ch) * LSEQ;
    const float* u1 = x + ((size_t)(2*p + 1) * DM + ch) * LSEQ;

    const int jb = tid + (tid >> 4);

    // P1 fwd: radix-32, S=512; pack u0 + i*u1; top half zero
    {
        cplx xv[32];
        #pragma unroll
        for (int r = 0; r < 16; r++) {
            const int i = tid + (r << 9);
            xv[r] = cpack(u0[i], u1[i]);
        }
        fft32_fwd<9, true>(xv, tid);
        #pragma unroll
        for (int r = 0; r < 32; r++) d[jb + 544 * r] = xv[r];
    }
    __syncthreads();

    const int j2 = tid & 15;
    const int b0 = (tid >> 4) * 544 + j2;

    // P2 fwd: radix-32, S=16
    {
        cplx xv[32];
        #pragma unroll
        for (int r = 0; r < 32; r++) xv[r] = d[b0 + 17 * r];
        fft32_fwd<4, false>(xv, j2);
        #pragma unroll
        for (int r = 0; r < 32; r++) d[b0 + 17 * r] = xv[r];
    }
    __syncthreads();

    // P3: const-twiddle fwd16 -> * Kf (D baked in) -> const-twiddle inv16
    const cplx* kf = g_Kf + (size_t)ch * NFFT;
    #pragma unroll
    for (int k = 0; k < 2; k++) {
        const int q  = tid + k * NT;
        const int pb = 17 * q;
        ulonglong2 kreg[8];
        const ulonglong2* kf2 = reinterpret_cast<const ulonglong2*>(kf + 16 * q);
        #pragma unroll
        for (int i = 0; i < 8; i++) kreg[i] = kf2[i];    // prefetch over fwd16
        cplx xv[16];
        #pragma unroll
        for (int r = 0; r < 16; r++) xv[r] = d[pb + r];
        fft16c_fwd(xv);
        #pragma unroll
        for (int i = 0; i < 8; i++) {
            xv[2*i]     = cmulc(xv[2*i],     kreg[i].x);
            xv[2*i + 1] = cmulc(xv[2*i + 1], kreg[i].y);
        }
        fft16c_inv(xv);
        #pragma unroll
        for (int r = 0; r < 16; r++) d[pb + r] = xv[r];
    }
    __syncthreads();

    // P2' inv
    {
        cplx xv[32];
        #pragma unroll
        for (int r = 0; r < 32; r++) xv[r] = d[b0 + 17 * r];
        fft32_inv<4, false>(xv, j2);
        #pragma unroll
        for (int r = 0; r < 32; r++) d[b0 + 17 * r] = xv[r];
    }
    __syncthreads();

    // P1' inv: half output, direct global store
    float* o0 = out + ((size_t)(2*p)     * DM + ch) * LSEQ;
    float* o1 = out + ((size_t)(2*p + 1) * DM + ch) * LSEQ;
    {
        cplx xv[32];
        #pragma unroll
        for (int r = 0; r < 32; r++) xv[r] = d[jb + 544 * r];
        fft32_inv<9, true>(xv, tid);
        #pragma unroll
        for (int r = 0; r < 16; r++) {
            const int i = tid + (r << 9);
            float a, b;
            cunpack(xv[r], a, b);
            o0[i] = a;
            o1[i] = b;
        }
    }
}

// ---------------- launch ----------------------------------------------------
// Input order (metadata): x, z, t, freq, W1, b1, W2, b2, W3, b3, Wout, deltas, D
extern "C" void kernel_launch(void* const* d_in, const int* in_sizes, int n_in,
                              void* d_out, int out_size) {
    (void)in_sizes; (void)n_in; (void)out_size;
    const float* x      = (const float*)d_in[0];
    const float* z      = (const float*)d_in[1];
    const float* t      = (const float*)d_in[2];
    const float* freq   = (const float*)d_in[3];
    const float* W1     = (const float*)d_in[4];
    const float* b1     = (const float*)d_in[5];
    const float* W2     = (const float*)d_in[6];
    const float* b2     = (const float*)d_in[7];
    const float* W3     = (const float*)d_in[8];
    const float* b3     = (const float*)d_in[9];
    const float* Wout   = (const float*)d_in[10];
    const float* deltas = (const float*)d_in[11];
    const float* Dbias  = (const float*)d_in[12];
    float* out = (float*)d_out;

    cudaFuncSetAttribute(kf_kernel,   cudaFuncAttributeMaxDynamicSharedMemorySize, SMEM_BYTES);
    cudaFuncSetAttribute(conv_kernel, cudaFuncAttributeMaxDynamicSharedMemorySize, SMEM_BYTES);

    mlp_kernel<<<LSEQ / 4, 256>>>(z, freq, W1, b1, W2, b2, W3, b3);
    filt_kernel<<<dim3(LSEQ / 32, DM / 128), 256>>>(Wout, t, deltas);
    kf_kernel<<<DM, NT, SMEM_BYTES>>>(Dbias);
    conv_kernel<<<dim3(DM, 2), NT, SMEM_BYTES>>>(x, out);
}